// round 3
// baseline (speedup 1.0000x reference)
#include <cuda_runtime.h>
#include <math.h>

// Problem dims (fixed by the reference)
#define Bb 8
#define Ss 2048
#define Hh 1024
#define Nst 256
#define Mm (Bb * Ss)   // 16384 rows

// ---------------------------------------------------------------------------
// Scratch (no cudaMalloc allowed): u[B,S,N], states[B,S,N], h[B,S,H]
// ---------------------------------------------------------------------------
__device__ float g_u[(size_t)Mm * Nst];
__device__ float g_states[(size_t)Mm * Nst];
__device__ float g_h[(size_t)Mm * Hh];

// ---------------------------------------------------------------------------
// Tiled fp32 GEMM:  C[M, Nsz] = A[M, K] @ W[Nsz, K]^T  (+ mode-specific epilogue)
//   MODE 0: dual-W (gate_w & B_w): u = clip(sigmoid(g + gate_b),0,1) * v  -> g_u
//   MODE 1: C-proj: h = acc + (D[n] + 1) * x[m,n]                         -> g_h
//   MODE 2: out-proj: out = acc + out_b[n]                                -> d_out
// ---------------------------------------------------------------------------
#define BM 64
#define BN 64
#define BK 16

template <int MODE>
__global__ __launch_bounds__(256)
void gemm_kernel(const float* __restrict__ A_in,   // MODE0: x   (others ignored)
                 const float* __restrict__ W1,
                 const float* __restrict__ W2,     // MODE0 only (B_w)
                 const float* __restrict__ bias,   // gate_b / D / out_b
                 const float* __restrict__ X,      // MODE1 only (x)
                 float* __restrict__ C_out,        // MODE2 only (d_out)
                 int K, int Nsz)
{
    __shared__ __align__(16) float As [BK][BM];
    __shared__ __align__(16) float Ws1[BK][BN];
    __shared__ __align__(16) float Ws2[BK][BN];

    const int tid = threadIdx.x;
    const int tx  = tid & 15;           // 0..15 -> 4 cols each
    const int ty  = tid >> 4;           // 0..15 -> 4 rows each
    const int m0  = blockIdx.y * BM;
    const int n0  = blockIdx.x * BN;

    const int lrow = tid >> 2;          // 0..63
    const int lcol = (tid & 3) << 2;    // 0,4,8,12

    // Resolve A / C by mode (scratch buffers are device globals)
    const float* A = (MODE == 0) ? A_in : (MODE == 1) ? g_states : g_h;
    float*       C = (MODE == 0) ? g_u  : (MODE == 1) ? g_h      : C_out;

    float acc1[4][4], acc2[4][4];
#pragma unroll
    for (int i = 0; i < 4; i++)
#pragma unroll
        for (int j = 0; j < 4; j++) { acc1[i][j] = 0.f; acc2[i][j] = 0.f; }

    const float* Aptr  = A  + (size_t)(m0 + lrow) * K + lcol;
    const float* W1ptr = W1 + (size_t)(n0 + lrow) * K + lcol;
    const float* W2ptr = (MODE == 0) ? (W2 + (size_t)(n0 + lrow) * K + lcol) : nullptr;

    for (int kt = 0; kt < K; kt += BK) {
        float4 av  = *(const float4*)(Aptr  + kt);
        float4 wv1 = *(const float4*)(W1ptr + kt);
        float4 wv2 = make_float4(0.f, 0.f, 0.f, 0.f);
        if (MODE == 0) wv2 = *(const float4*)(W2ptr + kt);

        __syncthreads();   // previous tile fully consumed
        As [lcol + 0][lrow] = av.x;  As [lcol + 1][lrow] = av.y;
        As [lcol + 2][lrow] = av.z;  As [lcol + 3][lrow] = av.w;
        Ws1[lcol + 0][lrow] = wv1.x; Ws1[lcol + 1][lrow] = wv1.y;
        Ws1[lcol + 2][lrow] = wv1.z; Ws1[lcol + 3][lrow] = wv1.w;
        if (MODE == 0) {
            Ws2[lcol + 0][lrow] = wv2.x; Ws2[lcol + 1][lrow] = wv2.y;
            Ws2[lcol + 2][lrow] = wv2.z; Ws2[lcol + 3][lrow] = wv2.w;
        }
        __syncthreads();

#pragma unroll
        for (int kk = 0; kk < BK; kk++) {
            float4 a4 = *(const float4*)&As [kk][ty << 2];
            float4 w4 = *(const float4*)&Ws1[kk][tx << 2];
            float ar[4] = { a4.x, a4.y, a4.z, a4.w };
            float w1[4] = { w4.x, w4.y, w4.z, w4.w };
            if (MODE == 0) {
                float4 v4 = *(const float4*)&Ws2[kk][tx << 2];
                float w2[4] = { v4.x, v4.y, v4.z, v4.w };
#pragma unroll
                for (int i = 0; i < 4; i++)
#pragma unroll
                    for (int j = 0; j < 4; j++) {
                        acc1[i][j] = fmaf(ar[i], w1[j], acc1[i][j]);
                        acc2[i][j] = fmaf(ar[i], w2[j], acc2[i][j]);
                    }
            } else {
#pragma unroll
                for (int i = 0; i < 4; i++)
#pragma unroll
                    for (int j = 0; j < 4; j++)
                        acc1[i][j] = fmaf(ar[i], w1[j], acc1[i][j]);
            }
        }
    }

#pragma unroll
    for (int i = 0; i < 4; i++) {
        const int m = m0 + (ty << 2) + i;
#pragma unroll
        for (int j = 0; j < 4; j++) {
            const int n = n0 + (tx << 2) + j;
            if (MODE == 0) {
                float gt = 1.0f / (1.0f + expf(-(acc1[i][j] + bias[n])));
                gt = fminf(fmaxf(gt, 0.0f), 1.0f);
                C[(size_t)m * Nsz + n] = gt * acc2[i][j];
            } else if (MODE == 1) {
                float xv = X[(size_t)m * Nsz + n];
                C[(size_t)m * Nsz + n] = acc1[i][j] + (bias[n] + 1.0f) * xv;
            } else {
                C[(size_t)m * Nsz + n] = acc1[i][j] + bias[n];
            }
        }
    }
}

// ---------------------------------------------------------------------------
// Sequential clipped scan: s_t = clip(A*s + u_t, -10, 10), per (b,n) chain.
// 2048 independent chains; 256 threads/block, 8 blocks.
// ---------------------------------------------------------------------------
__global__ __launch_bounds__(256)
void scan_kernel(const float* __restrict__ state0,
                 const float* __restrict__ A_log,
                 float* __restrict__ final_state)
{
    const int chain = blockIdx.x * 256 + threadIdx.x;   // 0..2047
    const int b = chain >> 8;          // /Nst
    const int n = chain & (Nst - 1);

    float Av = expf(A_log[n]);
    Av = fminf(fmaxf(Av, 0.5f), 0.99f);

    float s = state0[b * Nst + n];
    const float* up = g_u      + (size_t)b * Ss * Nst + n;
    float*       sp = g_states + (size_t)b * Ss * Nst + n;

#pragma unroll 4
    for (int t = 0; t < Ss; t++) {
        s = fminf(fmaxf(fmaf(Av, s, up[(size_t)t * Nst]), -10.0f), 10.0f);
        sp[(size_t)t * Nst] = s;
    }
    final_state[b * Nst + n] = s;
}

// ---------------------------------------------------------------------------
// LayerNorm over H=1024, in-place on g_h. One block (256 thr) per row.
// ---------------------------------------------------------------------------
__global__ __launch_bounds__(256)
void ln_kernel(const float* __restrict__ g, const float* __restrict__ bta)
{
    __shared__ float red[256];
    const int row = blockIdx.x;
    const int t   = threadIdx.x;
    float* hp = g_h + (size_t)row * Hh;

    float4 v = *(const float4*)(hp + (t << 2));

    red[t] = v.x + v.y + v.z + v.w;
    for (int off = 128; off; off >>= 1) {
        __syncthreads();
        if (t < off) red[t] += red[t + off];
    }
    __syncthreads();
    const float mu = red[0] * (1.0f / Hh);
    __syncthreads();

    float dx = v.x - mu, dy = v.y - mu, dz = v.z - mu, dw = v.w - mu;
    red[t] = dx * dx + dy * dy + dz * dz + dw * dw;
    for (int off = 128; off; off >>= 1) {
        __syncthreads();
        if (t < off) red[t] += red[t + off];
    }
    __syncthreads();
    const float inv = rsqrtf(red[0] * (1.0f / Hh) + 1e-5f);

    const int c = t << 2;
    float4 o;
    o.x = dx * inv * g[c + 0] + bta[c + 0];
    o.y = dy * inv * g[c + 1] + bta[c + 1];
    o.z = dz * inv * g[c + 2] + bta[c + 2];
    o.w = dw * inv * g[c + 3] + bta[c + 3];
    *(float4*)(hp + c) = o;
}

// ---------------------------------------------------------------------------
// Launch
// ---------------------------------------------------------------------------
extern "C" void kernel_launch(void* const* d_in, const int* in_sizes, int n_in,
                              void* d_out, int out_size)
{
    const float* x      = (const float*)d_in[0];
    const float* state0 = (const float*)d_in[1];
    const float* A_log  = (const float*)d_in[2];
    const float* B_w    = (const float*)d_in[3];
    const float* C_w    = (const float*)d_in[4];
    const float* Dv     = (const float*)d_in[5];
    const float* gate_w = (const float*)d_in[6];
    const float* gate_b = (const float*)d_in[7];
    const float* out_w  = (const float*)d_in[8];
    const float* out_b  = (const float*)d_in[9];
    const float* ln_g   = (const float*)d_in[10];
    const float* ln_b   = (const float*)d_in[11];

    float* out = (float*)d_out;
    float* final_state = out + (size_t)Mm * Hh;   // [B,N] tail

    // 1) u = clip(sigmoid(x@gate_w^T + gate_b),0,1) * (x@B_w^T)
    {
        dim3 grid(Nst / BN, Mm / BM);
        gemm_kernel<0><<<grid, 256>>>(x, gate_w, B_w, gate_b, nullptr, nullptr,
                                      Hh, Nst);
    }
    // 2) scan -> states, final_state
    scan_kernel<<<(Bb * Nst) / 256, 256>>>(state0, A_log, final_state);

    // 3) h = states@C_w^T + (D+1)*x
    {
        dim3 grid(Hh / BN, Mm / BM);
        gemm_kernel<1><<<grid, 256>>>(nullptr, C_w, nullptr, Dv, x, nullptr,
                                      Nst, Hh);
    }
    // 4) LayerNorm in place
    ln_kernel<<<Mm, 256>>>(ln_g, ln_b);

    // 5) out = hn@out_w^T + out_b
    {
        dim3 grid(Hh / BN, Mm / BM);
        gemm_kernel<2><<<grid, 256>>>(nullptr, out_w, nullptr, out_b, nullptr,
                                      out, Hh, Hh);
    }
}

// round 12
// speedup vs baseline: 1.1439x; 1.1439x over previous
#include <cuda_runtime.h>
#include <cuda_bf16.h>
#include <cstdint>
#include <cstddef>
#include <math.h>

// Problem dims
#define Bb 8
#define Ss 2048
#define Hh 1024
#define Nst 256
#define Mm (Bb * Ss)        // 16384

// GEMM tiling (warp-MMA; sm_103 baseline ISA only — tcgen05 needs 103a)
#define BM 128
#define BN 128
#define BK 32
#define ASTR 40                         // smem row stride in bf16 (80 B)
#define STAGE_BYTES (128 * ASTR * 2)

// ---------------------------------------------------------------------------
// Scratch (__device__ globals; no allocation allowed). All row-major.
// A-side split regions along K3: [hi | lo | hi]; W-side: [hi | hi | lo].
// ---------------------------------------------------------------------------
__device__ __align__(256) __nv_bfloat16 g_x3 [(size_t)Mm * 3 * Hh];   // x split
__device__ __align__(256) __nv_bfloat16 g_wg3[(size_t)512 * 3 * Hh];  // gate|B
__device__ __align__(256) float         g_uv [(size_t)Mm * 512];      // raw proj
__device__ __align__(256) __nv_bfloat16 g_s3 [(size_t)Mm * 3 * Nst];  // states split
__device__ __align__(256) __nv_bfloat16 g_wc3[(size_t)Hh * 3 * Nst];  // C_w
__device__ __align__(256) float         g_h  [(size_t)Mm * Hh];       // pre-LN h
__device__ __align__(256) __nv_bfloat16 g_hn3[(size_t)Mm * 3 * Hh];   // hn split
__device__ __align__(256) __nv_bfloat16 g_wo3[(size_t)Hh * 3 * Hh];   // out_w

// ---------------------------------------------------------------------------
// helpers
// ---------------------------------------------------------------------------
__device__ __forceinline__ uint32_t cvta_smem(const void* p) {
    uint32_t a;
    asm("{ .reg .u64 t; cvta.to.shared.u64 t, %1; cvt.u32.u64 %0, t; }"
        : "=r"(a) : "l"(p));
    return a;
}
__device__ __forceinline__ void ldsm4(uint32_t& r0, uint32_t& r1,
                                      uint32_t& r2, uint32_t& r3, uint32_t addr) {
    asm volatile("ldmatrix.sync.aligned.m8n8.x4.shared.b16 {%0,%1,%2,%3}, [%4];"
                 : "=r"(r0), "=r"(r1), "=r"(r2), "=r"(r3) : "r"(addr));
}
__device__ __forceinline__ void mma16816(float* d, const uint32_t* a, const uint32_t* b) {
    asm volatile(
        "mma.sync.aligned.m16n8k16.row.col.f32.bf16.bf16.f32 "
        "{%0,%1,%2,%3}, {%4,%5,%6,%7}, {%8,%9}, {%0,%1,%2,%3};"
        : "+f"(d[0]), "+f"(d[1]), "+f"(d[2]), "+f"(d[3])
        : "r"(a[0]), "r"(a[1]), "r"(a[2]), "r"(a[3]), "r"(b[0]), "r"(b[1]));
}
__device__ __forceinline__ void split_bf16(float v, __nv_bfloat16& hi, __nv_bfloat16& lo) {
    hi = __float2bfloat16(v);
    lo = __float2bfloat16(v - __bfloat162float(hi));
}

// ---------------------------------------------------------------------------
// Conversion: f32 [rows, K] row-major -> bf16 hi/lo split, row-major [rows, 3K].
// DSTSEL: 0 g_x3, 1 g_wg3, 2 g_wc3, 3 g_wo3.  IS_W selects region pattern.
// grid = rows*K/1024 blocks of 256 threads (1 float4 per thread).
// ---------------------------------------------------------------------------
template <int DSTSEL, int IS_W, int K>
__global__ __launch_bounds__(256)
void conv_kernel(const float* __restrict__ src, int row_base)
{
    __nv_bfloat16* dst = (DSTSEL == 0) ? g_x3 : (DSTSEL == 1) ? g_wg3
                       : (DSTSEL == 2) ? g_wc3 : g_wo3;
    const size_t i = (size_t)blockIdx.x * 256 + threadIdx.x;
    const float4 v = ((const float4*)src)[i];
    const size_t e = i * 4;
    const size_t row = e / K;
    const int k = (int)(e - row * K);

    const float f[4] = { v.x, v.y, v.z, v.w };
    __nv_bfloat16 hi[4], lo[4];
#pragma unroll
    for (int j = 0; j < 4; j++) split_bf16(f[j], hi[j], lo[j]);

    __nv_bfloat16* base = dst + (row_base + row) * (size_t)(3 * K) + k;
    *(uint2*)(base)         = *(const uint2*)hi;
    *(uint2*)(base + K)     = IS_W ? *(const uint2*)hi : *(const uint2*)lo;
    *(uint2*)(base + 2 * K) = IS_W ? *(const uint2*)lo : *(const uint2*)hi;
}

// ---------------------------------------------------------------------------
// Warp-MMA bf16 GEMM: C[M, Nsz] = A3[M, K3] @ W3[Nsz, K3]^T
//   MODE 0: C = g_uv  (ldc 512)
//   MODE 1: C = g_h = acc + (D[c]+1) * X[m,c]  (ldc 1024)
//   MODE 2: C = C_ext = acc + bias[c]          (ldc 1024)
// grid = (Nsz/128, M/128); block = 256 (8 warps; warp tile 64x32).
// ---------------------------------------------------------------------------
template <int MODE>
__global__ __launch_bounds__(256, 1)
void tgemm(float* __restrict__ C_ext, const float* __restrict__ bias,
           const float* __restrict__ X, const float* __restrict__ Dv, int K3)
{
    __shared__ __align__(128) __nv_bfloat16 sA[2][128 * ASTR];
    __shared__ __align__(128) __nv_bfloat16 sB[2][128 * ASTR];

    const __nv_bfloat16* A = (MODE == 0) ? g_x3  : (MODE == 1) ? g_s3  : g_hn3;
    const __nv_bfloat16* W = (MODE == 0) ? g_wg3 : (MODE == 1) ? g_wc3 : g_wo3;
    float* C = (MODE == 0) ? g_uv : (MODE == 1) ? g_h : C_ext;
    const int ldc = (MODE == 0) ? 512 : 1024;

    const int tid = threadIdx.x, lane = tid & 31, wid = tid >> 5;
    const int wm = wid & 1, wn = wid >> 1;
    const int m0 = blockIdx.y * BM, n0 = blockIdx.x * BN;

    // global load mapping: row = tid>>2 (+64), 16B-seg = tid&3
    const int grow = tid >> 2;
    const int gseg = tid & 3;
    const __nv_bfloat16* Ag = A + (size_t)(m0 + grow) * K3 + gseg * 8;
    const __nv_bfloat16* Wg = W + (size_t)(n0 + grow) * K3 + gseg * 8;
    const size_t rstep = (size_t)64 * K3;
    const int soff  = grow * ASTR + gseg * 8;
    const int soff2 = (grow + 64) * ASTR + gseg * 8;

    float acc[4][4][4];
#pragma unroll
    for (int i = 0; i < 4; i++)
#pragma unroll
        for (int j = 0; j < 4; j++)
#pragma unroll
            for (int q = 0; q < 4; q++) acc[i][j][q] = 0.f;

    const int NKT = K3 >> 5;

    // prologue: fill stage 0
    {
        uint4 a0 = *(const uint4*)Ag;
        uint4 a1 = *(const uint4*)(Ag + rstep);
        uint4 b0 = *(const uint4*)Wg;
        uint4 b1 = *(const uint4*)(Wg + rstep);
        *(uint4*)&sA[0][soff]  = a0;
        *(uint4*)&sA[0][soff2] = a1;
        *(uint4*)&sB[0][soff]  = b0;
        *(uint4*)&sB[0][soff2] = b1;
    }
    __syncthreads();

    const int lrow = lane & 15;
    const int lcol = (lane >> 4) << 3;
    const uint32_t aBase = cvta_smem(&sA[0][0]) + ((wm * 64 + lrow) * ASTR + lcol) * 2;
    const uint32_t bBase = cvta_smem(&sB[0][0]) + ((wn * 32 + lrow) * ASTR + lcol) * 2;

    for (int kt = 0; kt < NKT; kt++) {
        const int s = kt & 1;
        const bool more = (kt + 1 < NKT);
        uint4 na0, na1, nb0, nb1;
        if (more) {
            const __nv_bfloat16* Ap = Ag + (size_t)(kt + 1) * 32;
            const __nv_bfloat16* Wp = Wg + (size_t)(kt + 1) * 32;
            na0 = *(const uint4*)Ap;
            na1 = *(const uint4*)(Ap + rstep);
            nb0 = *(const uint4*)Wp;
            nb1 = *(const uint4*)(Wp + rstep);
        }
        const uint32_t aS = aBase + s * STAGE_BYTES;
        const uint32_t bS = bBase + s * STAGE_BYTES;
#pragma unroll
        for (int h = 0; h < 2; h++) {
            uint32_t a[4][4], b[4][2];
#pragma unroll
            for (int i = 0; i < 4; i++)
                ldsm4(a[i][0], a[i][1], a[i][2], a[i][3],
                      aS + (i * 16 * ASTR + h * 16) * 2);
#pragma unroll
            for (int jj = 0; jj < 2; jj++) {
                uint32_t r0, r1, r2, r3;
                ldsm4(r0, r1, r2, r3, bS + (jj * 16 * ASTR + h * 16) * 2);
                b[2 * jj][0] = r0; b[2 * jj][1] = r2;
                b[2 * jj + 1][0] = r1; b[2 * jj + 1][1] = r3;
            }
#pragma unroll
            for (int i = 0; i < 4; i++)
#pragma unroll
                for (int j = 0; j < 4; j++)
                    mma16816(acc[i][j], a[i], b[j]);
        }
        if (more) {
            __syncthreads();
            const int s1 = s ^ 1;
            *(uint4*)&sA[s1][soff]  = na0;
            *(uint4*)&sA[s1][soff2] = na1;
            *(uint4*)&sB[s1][soff]  = nb0;
            *(uint4*)&sB[s1][soff2] = nb1;
            __syncthreads();
        }
    }

    // epilogue: each thread owns (row, row+8) x 2 cols per (i,j) tile
#pragma unroll
    for (int i = 0; i < 4; i++) {
        const int r = m0 + wm * 64 + i * 16 + (lane >> 2);
#pragma unroll
        for (int j = 0; j < 4; j++) {
            const int c = n0 + wn * 32 + j * 8 + (lane & 3) * 2;
            float2 v0 = make_float2(acc[i][j][0], acc[i][j][1]);
            float2 v1 = make_float2(acc[i][j][2], acc[i][j][3]);
            if (MODE == 1) {
                const float2 dv = *(const float2*)(Dv + c);
                const float2 x0 = *(const float2*)(X + (size_t)r * 1024 + c);
                const float2 x1 = *(const float2*)(X + (size_t)(r + 8) * 1024 + c);
                v0.x += (dv.x + 1.0f) * x0.x;  v0.y += (dv.y + 1.0f) * x0.y;
                v1.x += (dv.x + 1.0f) * x1.x;  v1.y += (dv.y + 1.0f) * x1.y;
            } else if (MODE == 2) {
                const float2 bv = *(const float2*)(bias + c);
                v0.x += bv.x; v0.y += bv.y;
                v1.x += bv.x; v1.y += bv.y;
            }
            *(float2*)&C[(size_t)r * ldc + c]       = v0;
            *(float2*)&C[(size_t)(r + 8) * ldc + c] = v1;
        }
    }
}

// ---------------------------------------------------------------------------
// Fused gate + scan + state split: reads g_uv, writes g_s3 (hi|lo|hi) and
// final_state. 2048 independent chains.
// ---------------------------------------------------------------------------
__global__ __launch_bounds__(256)
void scan_kernel(const float* __restrict__ state0,
                 const float* __restrict__ A_log,
                 const float* __restrict__ gate_b,
                 float* __restrict__ final_state)
{
    const int chain = blockIdx.x * 256 + threadIdx.x;
    const int b = chain >> 8;
    const int n = chain & (Nst - 1);

    float Av = expf(A_log[n]);
    Av = fminf(fmaxf(Av, 0.5f), 0.99f);
    const float gb = gate_b[n];

    float s = state0[b * Nst + n];
    const float* uvp = g_uv + (size_t)b * Ss * 512 + n;
    __nv_bfloat16* sp = g_s3 + (size_t)b * Ss * (3 * Nst) + n;

#pragma unroll 4
    for (int t = 0; t < Ss; t++) {
        const float gl = uvp[(size_t)t * 512] + gb;
        const float ub = uvp[(size_t)t * 512 + 256];
        float sg = 1.0f / (1.0f + expf(-gl));
        sg = fminf(fmaxf(sg, 0.0f), 1.0f);
        s = fminf(fmaxf(fmaf(Av, s, sg * ub), -10.0f), 10.0f);
        __nv_bfloat16 hi, lo;
        split_bf16(s, hi, lo);
        sp[(size_t)t * 768]       = hi;
        sp[(size_t)t * 768 + 256] = lo;
        sp[(size_t)t * 768 + 512] = hi;
    }
    final_state[b * Nst + n] = s;
}

// ---------------------------------------------------------------------------
// LayerNorm over H=1024 with fused bf16 hi/lo split -> g_hn3
// ---------------------------------------------------------------------------
__global__ __launch_bounds__(256)
void ln_kernel(const float* __restrict__ g, const float* __restrict__ bta)
{
    __shared__ float red[256];
    const int row = blockIdx.x;
    const int t = threadIdx.x;
    const float* hp = g_h + (size_t)row * Hh;

    float4 v = *(const float4*)(hp + (t << 2));

    red[t] = v.x + v.y + v.z + v.w;
    for (int off = 128; off; off >>= 1) {
        __syncthreads();
        if (t < off) red[t] += red[t + off];
    }
    __syncthreads();
    const float mu = red[0] * (1.0f / Hh);
    __syncthreads();

    float dx = v.x - mu, dy = v.y - mu, dz = v.z - mu, dw = v.w - mu;
    red[t] = dx * dx + dy * dy + dz * dz + dw * dw;
    for (int off = 128; off; off >>= 1) {
        __syncthreads();
        if (t < off) red[t] += red[t + off];
    }
    __syncthreads();
    const float inv = rsqrtf(red[0] * (1.0f / Hh) + 1e-5f);

    const int c = t << 2;
    float o[4];
    o[0] = dx * inv * g[c + 0] + bta[c + 0];
    o[1] = dy * inv * g[c + 1] + bta[c + 1];
    o[2] = dz * inv * g[c + 2] + bta[c + 2];
    o[3] = dw * inv * g[c + 3] + bta[c + 3];

    __nv_bfloat16 hi[4], lo[4];
#pragma unroll
    for (int j = 0; j < 4; j++) split_bf16(o[j], hi[j], lo[j]);

    __nv_bfloat16* base = g_hn3 + (size_t)row * (3 * Hh) + c;
    *(uint2*)(base)          = *(const uint2*)hi;
    *(uint2*)(base + Hh)     = *(const uint2*)lo;
    *(uint2*)(base + 2 * Hh) = *(const uint2*)hi;
}

// ---------------------------------------------------------------------------
// Launch
// ---------------------------------------------------------------------------
extern "C" void kernel_launch(void* const* d_in, const int* in_sizes, int n_in,
                              void* d_out, int out_size)
{
    const float* x      = (const float*)d_in[0];
    const float* state0 = (const float*)d_in[1];
    const float* A_log  = (const float*)d_in[2];
    const float* B_w    = (const float*)d_in[3];
    const float* C_w    = (const float*)d_in[4];
    const float* Dv     = (const float*)d_in[5];
    const float* gate_w = (const float*)d_in[6];
    const float* gate_b = (const float*)d_in[7];
    const float* out_w  = (const float*)d_in[8];
    const float* out_b  = (const float*)d_in[9];
    const float* ln_g   = (const float*)d_in[10];
    const float* ln_b   = (const float*)d_in[11];

    float* out = (float*)d_out;
    float* final_state = out + (size_t)Mm * Hh;

    // 1) conversions: x -> g_x3; gate_w -> g_wg3[0:256); B_w -> g_wg3[256:512)
    conv_kernel<0, 0, 1024><<<Mm, 256>>>(x, 0);
    conv_kernel<1, 1, 1024><<<256, 256>>>(gate_w, 0);
    conv_kernel<1, 1, 1024><<<256, 256>>>(B_w, 256);

    // 2) GEMM0: g_uv[16384, 512] = x3 @ wg3^T   (K3 = 3072)
    tgemm<0><<<dim3(4, 128), 256>>>(nullptr, nullptr, nullptr, nullptr, 3 * Hh);

    // 3) fused gate + scan + split -> g_s3, final_state
    scan_kernel<<<(Bb * Nst) / 256, 256>>>(state0, A_log, gate_b, final_state);

    // 4) C_w -> g_wc3; GEMM1: g_h = s3 @ wc3^T + (D+1)*x   (K3 = 768)
    conv_kernel<2, 1, 256><<<256, 256>>>(C_w, 0);
    tgemm<1><<<dim3(8, 128), 256>>>(nullptr, nullptr, x, Dv, 3 * Nst);

    // 5) LN + split -> g_hn3
    ln_kernel<<<Mm, 256>>>(ln_g, ln_b);

    // 6) out_w -> g_wo3; GEMM2: out = hn3 @ wo3^T + out_b  (K3 = 3072)
    conv_kernel<3, 1, 1024><<<1024, 256>>>(out_w, 0);
    tgemm<2><<<dim3(8, 128), 256>>>(out, out_b, nullptr, nullptr, 3 * Hh);
}

// round 13
// speedup vs baseline: 1.3673x; 1.1953x over previous
#include <cuda_runtime.h>
#include <cuda_bf16.h>
#include <cstdint>
#include <cstddef>
#include <math.h>

// Problem dims
#define Bb 8
#define Ss 2048
#define Hh 1024
#define Nst 256
#define Mm (Bb * Ss)        // 16384

// GEMM tiling: CTA 128x256x32, 8 warps of 64x64, cp.async 4-stage
#define BM 128
#define BN 256
#define BK 32
#define ASTR 40                          // smem row stride in bf16 (80 B)
#define A_STAGE_B (128 * ASTR * 2)       // 10240 B
#define B_STAGE_B (256 * ASTR * 2)       // 20480 B
#define STAGE_B   (A_STAGE_B + B_STAGE_B)// 30720 B
#define NSTG 4
#define SMEM_TOTAL (NSTG * STAGE_B)      // 122880 B

// ---------------------------------------------------------------------------
// Scratch (__device__ globals). Row-major. A-side K3 regions [hi|lo|hi];
// W-side [hi|hi|lo].
// ---------------------------------------------------------------------------
__device__ __align__(256) __nv_bfloat16 g_x3 [(size_t)Mm * 3 * Hh];
__device__ __align__(256) __nv_bfloat16 g_wg3[(size_t)512 * 3 * Hh];
__device__ __align__(256) float         g_uv [(size_t)Mm * 512];
__device__ __align__(256) __nv_bfloat16 g_s3 [(size_t)Mm * 3 * Nst];
__device__ __align__(256) __nv_bfloat16 g_wc3[(size_t)Hh * 3 * Nst];
__device__ __align__(256) float         g_h  [(size_t)Mm * Hh];
__device__ __align__(256) __nv_bfloat16 g_hn3[(size_t)Mm * 3 * Hh];
__device__ __align__(256) __nv_bfloat16 g_wo3[(size_t)Hh * 3 * Hh];

// ---------------------------------------------------------------------------
// helpers
// ---------------------------------------------------------------------------
__device__ __forceinline__ uint32_t cvta_smem(const void* p) {
    uint32_t a;
    asm("{ .reg .u64 t; cvta.to.shared.u64 t, %1; cvt.u32.u64 %0, t; }"
        : "=r"(a) : "l"(p));
    return a;
}
__device__ __forceinline__ void ldsm4(uint32_t& r0, uint32_t& r1,
                                      uint32_t& r2, uint32_t& r3, uint32_t addr) {
    asm volatile("ldmatrix.sync.aligned.m8n8.x4.shared.b16 {%0,%1,%2,%3}, [%4];"
                 : "=r"(r0), "=r"(r1), "=r"(r2), "=r"(r3) : "r"(addr));
}
__device__ __forceinline__ void mma16816(float* d, const uint32_t* a, const uint32_t* b) {
    asm volatile(
        "mma.sync.aligned.m16n8k16.row.col.f32.bf16.bf16.f32 "
        "{%0,%1,%2,%3}, {%4,%5,%6,%7}, {%8,%9}, {%0,%1,%2,%3};"
        : "+f"(d[0]), "+f"(d[1]), "+f"(d[2]), "+f"(d[3])
        : "r"(a[0]), "r"(a[1]), "r"(a[2]), "r"(a[3]), "r"(b[0]), "r"(b[1]));
}
__device__ __forceinline__ void cpasync16(uint32_t dst, const void* src) {
    asm volatile("cp.async.cg.shared.global [%0], [%1], 16;"
                 :: "r"(dst), "l"(src));
}
__device__ __forceinline__ void cp_commit() {
    asm volatile("cp.async.commit_group;" ::: "memory");
}
__device__ __forceinline__ void cp_wait2() {
    asm volatile("cp.async.wait_group 2;" ::: "memory");
}
__device__ __forceinline__ void split_bf16(float v, __nv_bfloat16& hi, __nv_bfloat16& lo) {
    hi = __float2bfloat16(v);
    lo = __float2bfloat16(v - __bfloat162float(hi));
}

// ---------------------------------------------------------------------------
// Conversion: f32 [rows, K] -> bf16 hi/lo split [rows, 3K].
// DSTSEL: 0 g_x3, 1 g_wg3, 2 g_wc3, 3 g_wo3.
// ---------------------------------------------------------------------------
template <int DSTSEL, int IS_W, int K>
__global__ __launch_bounds__(256)
void conv_kernel(const float* __restrict__ src, int row_base)
{
    __nv_bfloat16* dst = (DSTSEL == 0) ? g_x3 : (DSTSEL == 1) ? g_wg3
                       : (DSTSEL == 2) ? g_wc3 : g_wo3;
    const size_t i = (size_t)blockIdx.x * 256 + threadIdx.x;
    const float4 v = ((const float4*)src)[i];
    const size_t e = i * 4;
    const size_t row = e / K;
    const int k = (int)(e - row * K);

    const float f[4] = { v.x, v.y, v.z, v.w };
    __nv_bfloat16 hi[4], lo[4];
#pragma unroll
    for (int j = 0; j < 4; j++) split_bf16(f[j], hi[j], lo[j]);

    __nv_bfloat16* base = dst + (row_base + row) * (size_t)(3 * K) + k;
    *(uint2*)(base)         = *(const uint2*)hi;
    *(uint2*)(base + K)     = IS_W ? *(const uint2*)hi : *(const uint2*)lo;
    *(uint2*)(base + 2 * K) = IS_W ? *(const uint2*)lo : *(const uint2*)hi;
}

// ---------------------------------------------------------------------------
// Pipelined warp-MMA bf16 GEMM: C[M, Nsz] = A3 @ W3^T
//   MODE 0: C = g_uv (ldc 512);  MODE 1: g_h = acc + (D+1)*X (ldc 1024)
//   MODE 2: C_ext = acc + bias (ldc 1024)
// grid = (Nsz/BN, M/BM); block = 256; dynamic smem.
// ---------------------------------------------------------------------------
template <int MODE>
__global__ __launch_bounds__(256, 1)
void tgemm(float* __restrict__ C_ext, const float* __restrict__ bias,
           const float* __restrict__ X, const float* __restrict__ Dv, int K3)
{
    extern __shared__ __align__(128) char smem[];
    const uint32_t sb = cvta_smem(smem);

    const __nv_bfloat16* A = (MODE == 0) ? g_x3  : (MODE == 1) ? g_s3  : g_hn3;
    const __nv_bfloat16* W = (MODE == 0) ? g_wg3 : (MODE == 1) ? g_wc3 : g_wo3;
    float* C = (MODE == 0) ? g_uv : (MODE == 1) ? g_h : C_ext;
    const int ldc = (MODE == 0) ? 512 : 1024;

    const int tid = threadIdx.x, lane = tid & 31, wid = tid >> 5;
    const int wm = wid & 1, wn = wid >> 1;          // 2 x 4 warp grid
    const int m0 = blockIdx.y * BM, n0 = blockIdx.x * BN;

    // cp.async source/dst mapping
    const int arow = tid >> 2;            // 0..63 (x2 rounds -> 128 rows)
    const int aseg = tid & 3;
    const __nv_bfloat16* Ag = A + (size_t)(m0 + arow) * K3 + aseg * 8;
    const __nv_bfloat16* Wg = W + (size_t)(n0 + arow) * K3 + aseg * 8;
    const size_t a64 = (size_t)64 * K3;
    const uint32_t aDst = sb + (arow * ASTR + aseg * 8) * 2;
    const uint32_t aDst2 = aDst + 64 * ASTR * 2;

    const int NKT = K3 >> 5;

    // issue copy of tile kt into stage s
    auto issue = [&](int s, int kt) {
        const uint32_t so = (uint32_t)(s * STAGE_B);
        const size_t ko = (size_t)kt * 32;
        cpasync16(aDst + so, Ag + ko);
        cpasync16(aDst2 + so, Ag + a64 + ko);
        const uint32_t bo = so + A_STAGE_B;
#pragma unroll
        for (int t = 0; t < 4; t++)
            cpasync16(aDst + bo - 0 + (uint32_t)(t * 64 * ASTR * 2),
                      Wg + (size_t)t * a64 + ko);
    };

    // prologue: stages 0..2
#pragma unroll
    for (int s = 0; s < 3; s++) { issue(s, s); cp_commit(); }

    float acc[4][8][4];
#pragma unroll
    for (int i = 0; i < 4; i++)
#pragma unroll
        for (int j = 0; j < 8; j++)
#pragma unroll
            for (int q = 0; q < 4; q++) acc[i][j][q] = 0.f;

    const int lrow = lane & 15;
    const int lcol = (lane >> 4) << 3;
    const uint32_t aBase = sb + ((wm * 64 + lrow) * ASTR + lcol) * 2;
    const uint32_t bBase = sb + A_STAGE_B + ((wn * 64 + lrow) * ASTR + lcol) * 2;

    for (int kt = 0; kt < NKT; kt++) {
        cp_wait2();
        __syncthreads();
        // refill the stage consumed 3 iters ago
        if (kt + 3 < NKT) issue((kt + 3) & 3, kt + 3);
        cp_commit();

        const uint32_t so = (uint32_t)((kt & 3) * STAGE_B);
        const uint32_t aS = aBase + so;
        const uint32_t bS = bBase + so;
#pragma unroll
        for (int h = 0; h < 2; h++) {
            uint32_t a[4][4], b[8][2];
#pragma unroll
            for (int i = 0; i < 4; i++)
                ldsm4(a[i][0], a[i][1], a[i][2], a[i][3],
                      aS + (i * 16 * ASTR + h * 16) * 2);
#pragma unroll
            for (int jj = 0; jj < 4; jj++) {
                uint32_t r0, r1, r2, r3;
                ldsm4(r0, r1, r2, r3, bS + (jj * 16 * ASTR + h * 16) * 2);
                b[2 * jj][0] = r0;     b[2 * jj][1] = r2;
                b[2 * jj + 1][0] = r1; b[2 * jj + 1][1] = r3;
            }
#pragma unroll
            for (int i = 0; i < 4; i++)
#pragma unroll
                for (int j = 0; j < 8; j++)
                    mma16816(acc[i][j], a[i], b[j]);
        }
    }

    // epilogue
#pragma unroll
    for (int i = 0; i < 4; i++) {
        const int r = m0 + wm * 64 + i * 16 + (lane >> 2);
#pragma unroll
        for (int j = 0; j < 8; j++) {
            const int c = n0 + wn * 64 + j * 8 + (lane & 3) * 2;
            float2 v0 = make_float2(acc[i][j][0], acc[i][j][1]);
            float2 v1 = make_float2(acc[i][j][2], acc[i][j][3]);
            if (MODE == 1) {
                const float2 dv = *(const float2*)(Dv + c);
                const float2 x0 = *(const float2*)(X + (size_t)r * 1024 + c);
                const float2 x1 = *(const float2*)(X + (size_t)(r + 8) * 1024 + c);
                v0.x += (dv.x + 1.0f) * x0.x;  v0.y += (dv.y + 1.0f) * x0.y;
                v1.x += (dv.x + 1.0f) * x1.x;  v1.y += (dv.y + 1.0f) * x1.y;
            } else if (MODE == 2) {
                const float2 bv = *(const float2*)(bias + c);
                v0.x += bv.x; v0.y += bv.y;
                v1.x += bv.x; v1.y += bv.y;
            }
            *(float2*)&C[(size_t)r * ldc + c]       = v0;
            *(float2*)&C[(size_t)(r + 8) * ldc + c] = v1;
        }
    }
}

// ---------------------------------------------------------------------------
// Fused gate + scan + state split -> g_s3 (hi|lo|hi), final_state
// ---------------------------------------------------------------------------
__global__ __launch_bounds__(256)
void scan_kernel(const float* __restrict__ state0,
                 const float* __restrict__ A_log,
                 const float* __restrict__ gate_b,
                 float* __restrict__ final_state)
{
    const int chain = blockIdx.x * 256 + threadIdx.x;
    const int b = chain >> 8;
    const int n = chain & (Nst - 1);

    float Av = expf(A_log[n]);
    Av = fminf(fmaxf(Av, 0.5f), 0.99f);
    const float gb = gate_b[n];

    float s = state0[b * Nst + n];
    const float* uvp = g_uv + (size_t)b * Ss * 512 + n;
    __nv_bfloat16* sp = g_s3 + (size_t)b * Ss * (3 * Nst) + n;

#pragma unroll 4
    for (int t = 0; t < Ss; t++) {
        const float gl = uvp[(size_t)t * 512] + gb;
        const float ub = uvp[(size_t)t * 512 + 256];
        float sg = 1.0f / (1.0f + expf(-gl));
        sg = fminf(fmaxf(sg, 0.0f), 1.0f);
        s = fminf(fmaxf(fmaf(Av, s, sg * ub), -10.0f), 10.0f);
        __nv_bfloat16 hi, lo;
        split_bf16(s, hi, lo);
        sp[(size_t)t * 768]       = hi;
        sp[(size_t)t * 768 + 256] = lo;
        sp[(size_t)t * 768 + 512] = hi;
    }
    final_state[b * Nst + n] = s;
}

// ---------------------------------------------------------------------------
// LayerNorm over H=1024 with fused hi/lo split -> g_hn3
// ---------------------------------------------------------------------------
__global__ __launch_bounds__(256)
void ln_kernel(const float* __restrict__ g, const float* __restrict__ bta)
{
    __shared__ float red[256];
    const int row = blockIdx.x;
    const int t = threadIdx.x;
    const float* hp = g_h + (size_t)row * Hh;

    float4 v = *(const float4*)(hp + (t << 2));

    red[t] = v.x + v.y + v.z + v.w;
    for (int off = 128; off; off >>= 1) {
        __syncthreads();
        if (t < off) red[t] += red[t + off];
    }
    __syncthreads();
    const float mu = red[0] * (1.0f / Hh);
    __syncthreads();

    float dx = v.x - mu, dy = v.y - mu, dz = v.z - mu, dw = v.w - mu;
    red[t] = dx * dx + dy * dy + dz * dz + dw * dw;
    for (int off = 128; off; off >>= 1) {
        __syncthreads();
        if (t < off) red[t] += red[t + off];
    }
    __syncthreads();
    const float inv = rsqrtf(red[0] * (1.0f / Hh) + 1e-5f);

    const int c = t << 2;
    float o[4];
    o[0] = dx * inv * g[c + 0] + bta[c + 0];
    o[1] = dy * inv * g[c + 1] + bta[c + 1];
    o[2] = dz * inv * g[c + 2] + bta[c + 2];
    o[3] = dw * inv * g[c + 3] + bta[c + 3];

    __nv_bfloat16 hi[4], lo[4];
#pragma unroll
    for (int j = 0; j < 4; j++) split_bf16(o[j], hi[j], lo[j]);

    __nv_bfloat16* base = g_hn3 + (size_t)row * (3 * Hh) + c;
    *(uint2*)(base)          = *(const uint2*)hi;
    *(uint2*)(base + Hh)     = *(const uint2*)lo;
    *(uint2*)(base + 2 * Hh) = *(const uint2*)hi;
}

// ---------------------------------------------------------------------------
// Launch
// ---------------------------------------------------------------------------
extern "C" void kernel_launch(void* const* d_in, const int* in_sizes, int n_in,
                              void* d_out, int out_size)
{
    const float* x      = (const float*)d_in[0];
    const float* state0 = (const float*)d_in[1];
    const float* A_log  = (const float*)d_in[2];
    const float* B_w    = (const float*)d_in[3];
    const float* C_w    = (const float*)d_in[4];
    const float* Dv     = (const float*)d_in[5];
    const float* gate_w = (const float*)d_in[6];
    const float* gate_b = (const float*)d_in[7];
    const float* out_w  = (const float*)d_in[8];
    const float* out_b  = (const float*)d_in[9];
    const float* ln_g   = (const float*)d_in[10];
    const float* ln_b   = (const float*)d_in[11];

    float* out = (float*)d_out;
    float* final_state = out + (size_t)Mm * Hh;

    cudaFuncSetAttribute(tgemm<0>, cudaFuncAttributeMaxDynamicSharedMemorySize, SMEM_TOTAL);
    cudaFuncSetAttribute(tgemm<1>, cudaFuncAttributeMaxDynamicSharedMemorySize, SMEM_TOTAL);
    cudaFuncSetAttribute(tgemm<2>, cudaFuncAttributeMaxDynamicSharedMemorySize, SMEM_TOTAL);

    // 1) conversions
    conv_kernel<0, 0, 1024><<<Mm, 256>>>(x, 0);
    conv_kernel<1, 1, 1024><<<256, 256>>>(gate_w, 0);
    conv_kernel<1, 1, 1024><<<256, 256>>>(B_w, 256);

    // 2) GEMM0: g_uv[16384, 512]   (K3 = 3072)
    tgemm<0><<<dim3(512 / BN, Mm / BM), 256, SMEM_TOTAL>>>(
        nullptr, nullptr, nullptr, nullptr, 3 * Hh);

    // 3) fused gate + scan + split
    scan_kernel<<<(Bb * Nst) / 256, 256>>>(state0, A_log, gate_b, final_state);

    // 4) GEMM1: g_h = s3 @ wc3^T + (D+1)*x   (K3 = 768)
    conv_kernel<2, 1, 256><<<256, 256>>>(C_w, 0);
    tgemm<1><<<dim3(Hh / BN, Mm / BM), 256, SMEM_TOTAL>>>(
        nullptr, nullptr, x, Dv, 3 * Nst);

    // 5) LN + split
    ln_kernel<<<Mm, 256>>>(ln_g, ln_b);

    // 6) GEMM2: out = hn3 @ wo3^T + out_b    (K3 = 3072)
    conv_kernel<3, 1, 1024><<<1024, 256>>>(out_w, 0);
    tgemm<2><<<dim3(Hh / BN, Mm / BM), 256, SMEM_TOTAL>>>(
        out, out_b, nullptr, nullptr, 3 * Hh);
}